// round 2
// baseline (speedup 1.0000x reference)
#include <cuda_runtime.h>
#include <cstdint>

// ---------------- problem constants ----------------
#define NB    64        // batch
#define SSEG  196       // segments
#define MP_   400       // max pixels per segment
#define ND    768       // embed dim
#define NCH   3         // channels
#define HW    50176     // 224*224
#define KPAD  1216      // 1200 padded to 38*32
#define KREAL 1200
#define MTOT  12544     // NB*SSEG
#define NCHUNK 98       // 50176/512
#define CPIX  512       // pixels per chunk

// GEMM tiling
#define BM 128
#define BN 128
#define BK 32
#define KCHUNKS 38      // KPAD/BK

// ---------------- scratch (device globals; no allocation) ----------------
__device__ float g_feats[(size_t)MTOT * KPAD];   // ~61 MB, A matrix [M, KPAD]
__device__ float g_Wt[(size_t)ND * KPAD];        // ~3.7 MB, B matrix [N, KPAD] (K-major, permuted)
__device__ int   g_hist[NB * NCHUNK * SSEG];     // ~4.9 MB, per-chunk histograms -> bases

__device__ __forceinline__ float rn_tf32(float v) {
    uint32_t r;
    asm("cvt.rna.tf32.f32 %0, %1;" : "=r"(r) : "f"(v));
    return __uint_as_float(r);
}

// ---------------- kernel 1: zero feats ----------------
__global__ void zero_feats_kernel() {
    size_t i = (size_t)blockIdx.x * blockDim.x + threadIdx.x;   // float4 index
    float4* p = reinterpret_cast<float4*>(g_feats);
    p[i] = make_float4(0.f, 0.f, 0.f, 0.f);
}

// ---------------- kernel 2: per-chunk segment histogram ----------------
__global__ void hist_kernel(const int* __restrict__ seg) {
    __shared__ int h[SSEG];
    const int b = blockIdx.y, chunk = blockIdx.x;
    const int t = threadIdx.x;
    if (t < SSEG) h[t] = 0;
    __syncthreads();
    const int p = chunk * CPIX + t;
    const int s = seg[(size_t)b * HW + p];
    atomicAdd(&h[s], 1);
    __syncthreads();
    if (t < SSEG) g_hist[((size_t)b * NCHUNK + chunk) * SSEG + t] = h[t];
}

// ---------------- kernel 3: exclusive scan over chunks per (b,s) ----------------
__global__ void scan_kernel() {
    const int idx = blockIdx.x * blockDim.x + threadIdx.x;
    if (idx >= NB * SSEG) return;
    const int b = idx / SSEG, s = idx - b * SSEG;
    int run = 0;
    int* base = &g_hist[(size_t)b * NCHUNK * SSEG + s];
#pragma unroll 7
    for (int c = 0; c < NCHUNK; c++) {
        int* ptr = base + (size_t)c * SSEG;
        int v = *ptr;
        *ptr = run;
        run += v;
    }
}

// ---------------- kernel 4: W -> Wt [N][KPAD], k = rank*3 + c permutation ----------------
__global__ void transpose_kernel(const float* __restrict__ Wsrc) {
    const int idx = blockIdx.x * blockDim.x + threadIdx.x;
    if (idx >= ND * KPAD) return;
    const int n = idx / KPAD, k = idx - n * KPAD;
    float v = 0.f;
    if (k < KREAL) {
        const int r = k / 3, c = k - 3 * r;           // k = r*3 + c
        v = Wsrc[(size_t)(c * MP_ + r) * ND + n];
    }
    g_Wt[(size_t)n * KPAD + k] = rn_tf32(v);
}

// ---------------- kernel 5: stable scatter of pixels into feats ----------------
__global__ void scatter_kernel(const float* __restrict__ img, const int* __restrict__ seg) {
    __shared__ int wh[16][SSEG];     // per-warp histograms
    const int b = blockIdx.y, chunk = blockIdx.x;
    const int t = threadIdx.x;
    const int w = t >> 5, l = t & 31;
    for (int i = t; i < 16 * SSEG; i += CPIX) (&wh[0][0])[i] = 0;
    __syncthreads();

    const int p = chunk * CPIX + t;
    const int s = seg[(size_t)b * HW + p];

    // stable intra-warp rank (lane order == pixel order)
    const unsigned mask = __match_any_sync(0xffffffffu, s);
    const int lt = __popc(mask & ((1u << l) - 1u));
    const int leader = __ffs(mask) - 1;
    if (l == leader) atomicAdd(&wh[w][s], __popc(mask));
    __syncthreads();

    int pre = 0;
    for (int ww = 0; ww < w; ww++) pre += wh[ww][s];

    const int rank = g_hist[((size_t)b * NCHUNK + chunk) * SSEG + s] + pre + lt;
    if (rank < MP_) {
        float* dst = g_feats + ((size_t)(b * SSEG + s)) * KPAD + rank * 3;
#pragma unroll
        for (int c = 0; c < NCH; c++) {
            const float v = img[((size_t)(b * NCH + c)) * HW + p];
            dst[c] = rn_tf32(v);
        }
    }
}

// ---------------- kernel 6: tf32 mma.sync GEMM: out = feats @ W + bias ----------------
// smem layout: [row][32] floats, element (r,k) at float index r*32 + (k ^ ((r&7)*4)).
// This makes every fragment-load pattern (a0..a3 / b0,b1 lane maps) a 32-bank bijection.
__device__ __forceinline__ int swz(int r, int k) {
    return r * BK + (k ^ ((r & 7) << 2));
}

__device__ __forceinline__ void mma_tf32(float* d, const uint32_t* a, uint32_t b0, uint32_t b1) {
    asm volatile(
        "mma.sync.aligned.m16n8k8.row.col.f32.tf32.tf32.f32 "
        "{%0,%1,%2,%3}, {%4,%5,%6,%7}, {%8,%9}, {%0,%1,%2,%3};"
        : "+f"(d[0]), "+f"(d[1]), "+f"(d[2]), "+f"(d[3])
        : "r"(a[0]), "r"(a[1]), "r"(a[2]), "r"(a[3]), "r"(b0), "r"(b1));
}

__device__ __forceinline__ void cp_async16(void* smem_dst, const void* gptr) {
    uint32_t sa;
    asm("{ .reg .u64 t; cvta.to.shared.u64 t, %1; cvt.u32.u64 %0, t; }" : "=r"(sa) : "l"(smem_dst));
    asm volatile("cp.async.cg.shared.global [%0], [%1], 16;" :: "r"(sa), "l"(gptr));
}

__global__ void __launch_bounds__(256, 1)
gemm_tf32_kernel(const float* __restrict__ bias, float* __restrict__ out) {
    __shared__ float sA[2][BM * BK];
    __shared__ float sB[2][BN * BK];

    const int tid = threadIdx.x;
    const int wid = tid >> 5, lane = tid & 31;
    const int warp_m = wid & 3;          // 4 warps over M (32 rows each)
    const int warp_n = wid >> 2;         // 2 warps over N (64 cols each)
    const int m0 = blockIdx.y * BM;
    const int n0 = blockIdx.x * BN;

    const float* Arow = g_feats + (size_t)m0 * KPAD;
    const float* Brow = g_Wt + (size_t)n0 * KPAD;

    // global->smem: 1024 float4 per tile, 4 per thread
    const int ldr = tid >> 3;            // row 0..127 (for q=0); +32 per q
    const int ldj = tid & 7;             // float4 column 0..7

    float acc[2][8][4];
#pragma unroll
    for (int i = 0; i < 2; i++)
#pragma unroll
        for (int j = 0; j < 8; j++)
#pragma unroll
            for (int v = 0; v < 4; v++) acc[i][j][v] = 0.f;

    auto issue_loads = [&](int buf, int kc) {
        const int kbase = kc * BK;
#pragma unroll
        for (int q = 0; q < 4; q++) {
            const int row = ldr + q * 32;
            const int so = swz(row, ldj * 4);
            cp_async16(&sA[buf][so], Arow + (size_t)row * KPAD + kbase + ldj * 4);
            cp_async16(&sB[buf][so], Brow + (size_t)row * KPAD + kbase + ldj * 4);
        }
        asm volatile("cp.async.commit_group;");
    };

    issue_loads(0, 0);

    for (int kc = 0; kc < KCHUNKS; kc++) {
        const int buf = kc & 1;
        if (kc + 1 < KCHUNKS) {
            issue_loads(buf ^ 1, kc + 1);
            asm volatile("cp.async.wait_group 1;");
        } else {
            asm volatile("cp.async.wait_group 0;");
        }
        __syncthreads();

        const float* As = sA[buf];
        const float* Bs = sB[buf];
        const int lr = lane >> 2;        // 0..7
        const int lc = lane & 3;         // 0..3
#pragma unroll
        for (int s = 0; s < 4; s++) {
            const int k0 = s * 8 + lc;
            uint32_t a[2][4];
#pragma unroll
            for (int i = 0; i < 2; i++) {
                const int r = warp_m * 32 + i * 16 + lr;
                a[i][0] = __float_as_uint(As[swz(r, k0)]);
                a[i][1] = __float_as_uint(As[swz(r + 8, k0)]);
                a[i][2] = __float_as_uint(As[swz(r, k0 + 4)]);
                a[i][3] = __float_as_uint(As[swz(r + 8, k0 + 4)]);
            }
#pragma unroll
            for (int j = 0; j < 8; j++) {
                const int n = warp_n * 64 + j * 8 + lr;
                const uint32_t b0 = __float_as_uint(Bs[swz(n, k0)]);
                const uint32_t b1 = __float_as_uint(Bs[swz(n, k0 + 4)]);
                mma_tf32(acc[0][j], a[0], b0, b1);
                mma_tf32(acc[1][j], a[1], b0, b1);
            }
        }
        __syncthreads();
    }

    // epilogue: D(16x8) thread map: d0,d1 at (lane/4, (lane&3)*2 +0/1), d2,d3 at row+8
    const int lr = lane >> 2, lc = lane & 3;
#pragma unroll
    for (int i = 0; i < 2; i++) {
        const int row = m0 + warp_m * 32 + i * 16 + lr;
#pragma unroll
        for (int j = 0; j < 8; j++) {
            const int col = n0 + warp_n * 64 + j * 8 + lc * 2;
            const float2 bv = *reinterpret_cast<const float2*>(bias + col);
            float2 lo, hi;
            lo.x = acc[i][j][0] + bv.x;
            lo.y = acc[i][j][1] + bv.y;
            hi.x = acc[i][j][2] + bv.x;
            hi.y = acc[i][j][3] + bv.y;
            *reinterpret_cast<float2*>(out + (size_t)row * ND + col) = lo;
            *reinterpret_cast<float2*>(out + (size_t)(row + 8) * ND + col) = hi;
        }
    }
}

// ---------------- launch ----------------
extern "C" void kernel_launch(void* const* d_in, const int* in_sizes, int n_in,
                              void* d_out, int out_size) {
    (void)in_sizes; (void)n_in; (void)out_size;
    const float* img  = (const float*)d_in[0];
    const int*   seg  = (const int*)d_in[1];
    const float* Wsrc = (const float*)d_in[2];
    const float* bias = (const float*)d_in[3];
    float* out = (float*)d_out;

    // feats = MTOT*KPAD floats = 15,253,504 = 14896 * 256 float4
    zero_feats_kernel<<<14896, 256>>>();
    hist_kernel<<<dim3(NCHUNK, NB), CPIX>>>(seg);
    scan_kernel<<<(NB * SSEG + 255) / 256, 256>>>();
    transpose_kernel<<<(ND * KPAD + 255) / 256, 256>>>(Wsrc);
    scatter_kernel<<<dim3(NCHUNK, NB), CPIX>>>(img, seg);
    gemm_tf32_kernel<<<dim3(ND / BN, MTOT / BM), 256>>>(bias, out);
}

// round 3
// speedup vs baseline: 1.0825x; 1.0825x over previous
#include <cuda_runtime.h>
#include <cstdint>

// ---------------- problem constants ----------------
#define NB    64        // batch
#define SSEG  196       // segments
#define MP_   400       // max pixels per segment
#define ND    768       // embed dim
#define NCH   3         // channels
#define HW    50176     // 224*224
#define KPAD  1216      // 1200 padded to 38*32
#define KREAL 1200
#define MTOT  12544     // NB*SSEG
#define NCHUNK 98       // 50176/512
#define CPIX  512       // pixels per chunk

// GEMM tiling
#define BM 128
#define BN 128
#define BK 32
#define KCHUNKS 38      // KPAD/BK

// ---------------- scratch (device globals; no allocation) ----------------
__device__ float g_feats[(size_t)MTOT * KPAD];   // ~61 MB, A matrix [M, KPAD]
__device__ float g_Wt[(size_t)ND * KPAD];        // ~3.7 MB, B matrix [N, KPAD] (K-major, permuted)
__device__ int   g_hist[NB * NCHUNK * SSEG];     // ~4.9 MB, per-chunk histograms -> bases

__device__ __forceinline__ float rn_tf32(float v) {
    uint32_t r;
    asm("cvt.rna.tf32.f32 %0, %1;" : "=r"(r) : "f"(v));
    return __uint_as_float(r);
}

// ---------------- kernel 1: zero feats ----------------
__global__ void zero_feats_kernel() {
    size_t i = (size_t)blockIdx.x * blockDim.x + threadIdx.x;   // float4 index
    float4* p = reinterpret_cast<float4*>(g_feats);
    p[i] = make_float4(0.f, 0.f, 0.f, 0.f);
}

// ---------------- kernel 2: per-chunk segment histogram ----------------
__global__ void hist_kernel(const int* __restrict__ seg) {
    __shared__ int h[SSEG];
    const int b = blockIdx.y, chunk = blockIdx.x;
    const int t = threadIdx.x;
    if (t < SSEG) h[t] = 0;
    __syncthreads();
    const int p = chunk * CPIX + t;
    const int s = seg[(size_t)b * HW + p];
    atomicAdd(&h[s], 1);
    __syncthreads();
    if (t < SSEG) g_hist[((size_t)b * NCHUNK + chunk) * SSEG + t] = h[t];
}

// ---------------- kernel 3: exclusive scan over chunks per (b,s) ----------------
__global__ void scan_kernel() {
    const int idx = blockIdx.x * blockDim.x + threadIdx.x;
    if (idx >= NB * SSEG) return;
    const int b = idx / SSEG, s = idx - b * SSEG;
    int run = 0;
    int* base = &g_hist[(size_t)b * NCHUNK * SSEG + s];
#pragma unroll 7
    for (int c = 0; c < NCHUNK; c++) {
        int* ptr = base + (size_t)c * SSEG;
        int v = *ptr;
        *ptr = run;
        run += v;
    }
}

// ---------------- kernel 4: W -> Wt [N][KPAD], k = rank*3 + c permutation ----------------
__global__ void transpose_kernel(const float* __restrict__ Wsrc) {
    const int idx = blockIdx.x * blockDim.x + threadIdx.x;
    if (idx >= ND * KPAD) return;
    const int n = idx / KPAD, k = idx - n * KPAD;
    float v = 0.f;
    if (k < KREAL) {
        const int r = k / 3, c = k - 3 * r;           // k = r*3 + c
        v = Wsrc[(size_t)(c * MP_ + r) * ND + n];
    }
    g_Wt[(size_t)n * KPAD + k] = rn_tf32(v);
}

// ---------------- kernel 5: stable scatter of pixels into feats ----------------
__global__ void scatter_kernel(const float* __restrict__ img, const int* __restrict__ seg) {
    __shared__ int wh[16][SSEG];     // per-warp histograms
    const int b = blockIdx.y, chunk = blockIdx.x;
    const int t = threadIdx.x;
    const int w = t >> 5, l = t & 31;
    for (int i = t; i < 16 * SSEG; i += CPIX) (&wh[0][0])[i] = 0;
    __syncthreads();

    const int p = chunk * CPIX + t;
    const int s = seg[(size_t)b * HW + p];

    // stable intra-warp rank (lane order == pixel order)
    const unsigned mask = __match_any_sync(0xffffffffu, s);
    const int lt = __popc(mask & ((1u << l) - 1u));
    const int leader = __ffs(mask) - 1;
    if (l == leader) atomicAdd(&wh[w][s], __popc(mask));
    __syncthreads();

    int pre = 0;
    for (int ww = 0; ww < w; ww++) pre += wh[ww][s];

    const int rank = g_hist[((size_t)b * NCHUNK + chunk) * SSEG + s] + pre + lt;
    if (rank < MP_) {
        float* dst = g_feats + ((size_t)(b * SSEG + s)) * KPAD + rank * 3;
#pragma unroll
        for (int c = 0; c < NCH; c++) {
            const float v = img[((size_t)(b * NCH + c)) * HW + p];
            dst[c] = rn_tf32(v);
        }
    }
}

// ---------------- kernel 6: tf32 mma.sync GEMM with ldmatrix feeds ----------------
// smem layout: [row][32] floats, element (r,k) at float index r*32 + (k ^ ((r&7)*4)).
// Every 4-aligned k-group of 4 floats stays contiguous (xor touches bits>=2 only),
// so each 16B group is an ldmatrix row; the pattern is a 32-bank bijection.
__device__ __forceinline__ int swz(int r, int k) {
    return r * BK + (k ^ ((r & 7) << 2));
}

__device__ __forceinline__ void mma_tf32(float* d, const uint32_t* a, uint32_t b0, uint32_t b1) {
    asm volatile(
        "mma.sync.aligned.m16n8k8.row.col.f32.tf32.tf32.f32 "
        "{%0,%1,%2,%3}, {%4,%5,%6,%7}, {%8,%9}, {%0,%1,%2,%3};"
        : "+f"(d[0]), "+f"(d[1]), "+f"(d[2]), "+f"(d[3])
        : "r"(a[0]), "r"(a[1]), "r"(a[2]), "r"(a[3]), "r"(b0), "r"(b1));
}

__device__ __forceinline__ void ldsm4(uint32_t& r0, uint32_t& r1, uint32_t& r2, uint32_t& r3,
                                      uint32_t addr) {
    asm volatile("ldmatrix.sync.aligned.m8n8.x4.shared.b16 {%0,%1,%2,%3}, [%4];"
                 : "=r"(r0), "=r"(r1), "=r"(r2), "=r"(r3) : "r"(addr));
}

__device__ __forceinline__ void cp_async16(void* smem_dst, const void* gptr) {
    uint32_t sa;
    asm("{ .reg .u64 t; cvta.to.shared.u64 t, %1; cvt.u32.u64 %0, t; }" : "=r"(sa) : "l"(smem_dst));
    asm volatile("cp.async.cg.shared.global [%0], [%1], 16;" :: "r"(sa), "l"(gptr));
}

__global__ void __launch_bounds__(256)
gemm_tf32_kernel(const float* __restrict__ bias, float* __restrict__ out) {
    __shared__ float sA[2][BM * BK];
    __shared__ float sB[2][BN * BK];

    const int tid = threadIdx.x;
    const int wid = tid >> 5, lane = tid & 31;
    const int warp_m = wid & 3;          // 4 warps over M (32 rows each)
    const int warp_n = wid >> 2;         // 2 warps over N (64 cols each)
    const int m0 = blockIdx.y * BM;
    const int n0 = blockIdx.x * BN;

    const float* Arow = g_feats + (size_t)m0 * KPAD;
    const float* Brow = g_Wt + (size_t)n0 * KPAD;

    // global->smem: 1024 float4 per tile, 4 per thread
    const int ldr = tid >> 3;            // row 0..31 block (+32 per q)
    const int ldj = tid & 7;             // float4 column 0..7

    float acc[2][8][4];
#pragma unroll
    for (int i = 0; i < 2; i++)
#pragma unroll
        for (int j = 0; j < 8; j++)
#pragma unroll
            for (int v = 0; v < 4; v++) acc[i][j][v] = 0.f;

    auto issue_loads = [&](int buf, int kc) {
        const int kbase = kc * BK;
#pragma unroll
        for (int q = 0; q < 4; q++) {
            const int row = ldr + q * 32;
            const int so = swz(row, ldj * 4);
            cp_async16(&sA[buf][so], Arow + (size_t)row * KPAD + kbase + ldj * 4);
            cp_async16(&sB[buf][so], Brow + (size_t)row * KPAD + kbase + ldj * 4);
        }
        asm volatile("cp.async.commit_group;");
    };

    // ---- ldmatrix per-lane address precompute (byte offsets within a buffer) ----
    uint32_t sAu, sBu;
    asm("{ .reg .u64 t; cvta.to.shared.u64 t, %1; cvt.u32.u64 %0, t; }" : "=r"(sAu) : "l"((void*)sA));
    asm("{ .reg .u64 t; cvta.to.shared.u64 t, %1; cvt.u32.u64 %0, t; }" : "=r"(sBu) : "l"((void*)sB));

    const int xb = (lane & 7) << 2;                  // swizzle xor (elements), same for A and B rows
    // A: matrices {rows r..r+7 | r+8..r+15} x {k0..3 | k4..7}; lanes: row = base + (lane&15),
    //    k-chunk = (lane>>4)*4
    const int rowA = warp_m * 32 + (lane & 15);
    const int aChunk = (lane >> 4) << 2;             // 0 or 4 (elements)
    const uint32_t aBase = sAu + (uint32_t)rowA * 128;
    // B: matrices {rows n..n+7 k0..3 | n..n+7 k4..7 | n+8.. k0..3 | n+8.. k4..7}
    //    row = base + ((lane>>4)<<3) + (lane&7), k-chunk = ((lane>>3)&1)*4
    const int rowBoff = ((lane >> 4) << 3) + (lane & 7);
    const int bChunk = ((lane >> 3) & 1) << 2;       // 0 or 4 (elements)
    uint32_t bBase[4];
#pragma unroll
    for (int jp = 0; jp < 4; jp++)
        bBase[jp] = sBu + (uint32_t)(warp_n * 64 + jp * 16 + rowBoff) * 128;

    issue_loads(0, 0);

    for (int kc = 0; kc < KCHUNKS; kc++) {
        const int buf = kc & 1;
        if (kc + 1 < KCHUNKS) {
            issue_loads(buf ^ 1, kc + 1);
            asm volatile("cp.async.wait_group 1;");
        } else {
            asm volatile("cp.async.wait_group 0;");
        }
        __syncthreads();

        const uint32_t bo = (uint32_t)buf * 16384u;
#pragma unroll
        for (int s = 0; s < 4; s++) {
            const uint32_t aOff = (uint32_t)(((s * 8 + aChunk) ^ xb) << 2);
            uint32_t a0[4], a1[4];
            ldsm4(a0[0], a0[1], a0[2], a0[3], aBase + bo + aOff);
            ldsm4(a1[0], a1[1], a1[2], a1[3], aBase + bo + aOff + 16 * 128);
            const uint32_t bOff = (uint32_t)(((s * 8 + bChunk) ^ xb) << 2);
#pragma unroll
            for (int jp = 0; jp < 4; jp++) {
                uint32_t b0, b1, b2, b3;
                ldsm4(b0, b1, b2, b3, bBase[jp] + bo + bOff);
                mma_tf32(acc[0][2 * jp],     a0, b0, b1);
                mma_tf32(acc[1][2 * jp],     a1, b0, b1);
                mma_tf32(acc[0][2 * jp + 1], a0, b2, b3);
                mma_tf32(acc[1][2 * jp + 1], a1, b2, b3);
            }
        }
        __syncthreads();
    }

    // epilogue: D(16x8) thread map: d0,d1 at (lane/4, (lane&3)*2 +0/1), d2,d3 at row+8
    const int lr = lane >> 2, lc = lane & 3;
#pragma unroll
    for (int i = 0; i < 2; i++) {
        const int row = m0 + warp_m * 32 + i * 16 + lr;
#pragma unroll
        for (int j = 0; j < 8; j++) {
            const int col = n0 + warp_n * 64 + j * 8 + lc * 2;
            const float2 bv = *reinterpret_cast<const float2*>(bias + col);
            float2 lo, hi;
            lo.x = acc[i][j][0] + bv.x;
            lo.y = acc[i][j][1] + bv.y;
            hi.x = acc[i][j][2] + bv.x;
            hi.y = acc[i][j][3] + bv.y;
            *reinterpret_cast<float2*>(out + (size_t)row * ND + col) = lo;
            *reinterpret_cast<float2*>(out + (size_t)(row + 8) * ND + col) = hi;
        }
    }
}

// ---------------- launch ----------------
extern "C" void kernel_launch(void* const* d_in, const int* in_sizes, int n_in,
                              void* d_out, int out_size) {
    (void)in_sizes; (void)n_in; (void)out_size;
    const float* img  = (const float*)d_in[0];
    const int*   seg  = (const int*)d_in[1];
    const float* Wsrc = (const float*)d_in[2];
    const float* bias = (const float*)d_in[3];
    float* out = (float*)d_out;

    // feats = MTOT*KPAD floats = 15,253,504 = 14896 * 256 float4
    zero_feats_kernel<<<14896, 256>>>();
    hist_kernel<<<dim3(NCHUNK, NB), CPIX>>>(seg);
    scan_kernel<<<(NB * SSEG + 255) / 256, 256>>>();
    transpose_kernel<<<(ND * KPAD + 255) / 256, 256>>>(Wsrc);
    scatter_kernel<<<dim3(NCHUNK, NB), CPIX>>>(img, seg);
    gemm_tf32_kernel<<<dim3(ND / BN, MTOT / BM), 256>>>(bias, out);
}

// round 4
// speedup vs baseline: 1.1916x; 1.1008x over previous
#include <cuda_runtime.h>
#include <cstdint>

// ---------------- problem constants ----------------
#define NB    64        // batch
#define SSEG  196       // segments
#define MP_   400       // max pixels per segment
#define ND    768       // embed dim
#define NCH   3         // channels
#define HW    50176     // 224*224
#define KPAD  1216      // 1200 padded to 38*32
#define KREAL 1200
#define MTOT  12544     // NB*SSEG
#define NCHUNK 98       // 50176/512
#define CPIX  512       // pixels per chunk

// GEMM tiling
#define BM 128
#define BN 128
#define BK 32

// ---------------- scratch (device globals; no allocation) ----------------
__device__ float g_feats[(size_t)MTOT * KPAD];   // ~61 MB, A matrix [M, KPAD]
__device__ float g_Wt[(size_t)ND * KPAD];        // ~3.7 MB, B matrix [N, KPAD] (K-major, permuted)
__device__ int   g_hist[NB * NCHUNK * SSEG];     // ~4.9 MB, per-chunk histograms -> bases
__device__ int   g_cnt[MTOT];                    // per-(b,s) pixel count
__device__ int   g_kmax;                         // max over rows of 3*min(cnt,MP)

__device__ __forceinline__ float rn_tf32(float v) {
    uint32_t r;
    asm("cvt.rna.tf32.f32 %0, %1;" : "=r"(r) : "f"(v));
    return __uint_as_float(r);
}

// ---------------- kernel 1: per-chunk segment histogram (+ reset g_kmax) ----------------
__global__ void hist_kernel(const int* __restrict__ seg) {
    __shared__ int h[SSEG];
    const int b = blockIdx.y, chunk = blockIdx.x;
    const int t = threadIdx.x;
    if (b == 0 && chunk == 0 && t == 0) g_kmax = 0;
    if (t < SSEG) h[t] = 0;
    __syncthreads();
    const int p = chunk * CPIX + t;
    const int s = seg[(size_t)b * HW + p];
    atomicAdd(&h[s], 1);
    __syncthreads();
    if (t < SSEG) g_hist[((size_t)b * NCHUNK + chunk) * SSEG + t] = h[t];
}

// ---------------- kernel 2: exclusive scan over chunks per (b,s); counts + kmax ----------------
__global__ void scan_kernel() {
    const int idx = blockIdx.x * blockDim.x + threadIdx.x;
    if (idx >= NB * SSEG) return;
    const int b = idx / SSEG, s = idx - b * SSEG;
    int run = 0;
    int* base = &g_hist[(size_t)b * NCHUNK * SSEG + s];
#pragma unroll 7
    for (int c = 0; c < NCHUNK; c++) {
        int* ptr = base + (size_t)c * SSEG;
        int v = *ptr;
        *ptr = run;
        run += v;
    }
    g_cnt[idx] = run;
    const int keff = (run < MP_ ? run : MP_) * 3;
    atomicMax(&g_kmax, keff);
}

// ---------------- kernel 3: W -> Wt [N][KPAD], k = rank*3 + c permutation ----------------
__global__ void transpose_kernel(const float* __restrict__ Wsrc) {
    const int idx = blockIdx.x * blockDim.x + threadIdx.x;
    if (idx >= ND * KPAD) return;
    const int n = idx / KPAD, k = idx - n * KPAD;
    float v = 0.f;
    if (k < KREAL) {
        const int r = k / 3, c = k - 3 * r;           // k = r*3 + c
        v = Wsrc[(size_t)(c * MP_ + r) * ND + n];
    }
    g_Wt[(size_t)n * KPAD + k] = rn_tf32(v);
}

// ---------------- kernel 4: zero only the unwritten tail of each feats row ----------------
__global__ void tail_zero_kernel() {
    const int row = blockIdx.x;
    int cnt = g_cnt[row];
    if (cnt > MP_) cnt = MP_;
    float* dst = g_feats + (size_t)row * KPAD;
    for (int k = 3 * cnt + threadIdx.x; k < KPAD; k += blockDim.x) dst[k] = 0.f;
}

// ---------------- kernel 5: stable scatter of pixels into feats ----------------
__global__ void scatter_kernel(const float* __restrict__ img, const int* __restrict__ seg) {
    __shared__ int wh[16][SSEG];     // per-warp histograms
    const int b = blockIdx.y, chunk = blockIdx.x;
    const int t = threadIdx.x;
    const int w = t >> 5, l = t & 31;
    for (int i = t; i < 16 * SSEG; i += CPIX) (&wh[0][0])[i] = 0;
    __syncthreads();

    const int p = chunk * CPIX + t;
    const int s = seg[(size_t)b * HW + p];

    // stable intra-warp rank (lane order == pixel order)
    const unsigned mask = __match_any_sync(0xffffffffu, s);
    const int lt = __popc(mask & ((1u << l) - 1u));
    const int leader = __ffs(mask) - 1;
    if (l == leader) atomicAdd(&wh[w][s], __popc(mask));
    __syncthreads();

    int pre = 0;
    for (int ww = 0; ww < w; ww++) pre += wh[ww][s];

    const int rank = g_hist[((size_t)b * NCHUNK + chunk) * SSEG + s] + pre + lt;
    if (rank < MP_) {
        float* dst = g_feats + ((size_t)(b * SSEG + s)) * KPAD + rank * 3;
#pragma unroll
        for (int c = 0; c < NCH; c++) {
            const float v = img[((size_t)(b * NCH + c)) * HW + p];
            dst[c] = rn_tf32(v);
        }
    }
}

// ---------------- kernel 6: tf32 mma.sync GEMM with ldmatrix feeds, dynamic K ----------------
// smem layout: [row][32] floats, element (r,k) at float index r*32 + (k ^ ((r&7)*4)).
__device__ __forceinline__ int swz(int r, int k) {
    return r * BK + (k ^ ((r & 7) << 2));
}

__device__ __forceinline__ void mma_tf32(float* d, const uint32_t* a, uint32_t b0, uint32_t b1) {
    asm volatile(
        "mma.sync.aligned.m16n8k8.row.col.f32.tf32.tf32.f32 "
        "{%0,%1,%2,%3}, {%4,%5,%6,%7}, {%8,%9}, {%0,%1,%2,%3};"
        : "+f"(d[0]), "+f"(d[1]), "+f"(d[2]), "+f"(d[3])
        : "r"(a[0]), "r"(a[1]), "r"(a[2]), "r"(a[3]), "r"(b0), "r"(b1));
}

__device__ __forceinline__ void ldsm4(uint32_t& r0, uint32_t& r1, uint32_t& r2, uint32_t& r3,
                                      uint32_t addr) {
    asm volatile("ldmatrix.sync.aligned.m8n8.x4.shared.b16 {%0,%1,%2,%3}, [%4];"
                 : "=r"(r0), "=r"(r1), "=r"(r2), "=r"(r3) : "r"(addr));
}

__device__ __forceinline__ void cp_async16(void* smem_dst, const void* gptr) {
    uint32_t sa;
    asm("{ .reg .u64 t; cvta.to.shared.u64 t, %1; cvt.u32.u64 %0, t; }" : "=r"(sa) : "l"(smem_dst));
    asm volatile("cp.async.cg.shared.global [%0], [%1], 16;" :: "r"(sa), "l"(gptr));
}

__global__ void __launch_bounds__(256)
gemm_tf32_kernel(const float* __restrict__ bias, float* __restrict__ out) {
    __shared__ float sA[2][BM * BK];
    __shared__ float sB[2][BN * BK];

    const int tid = threadIdx.x;
    const int wid = tid >> 5, lane = tid & 31;
    const int warp_m = wid & 3;          // 4 warps over M (32 rows each)
    const int warp_n = wid >> 2;         // 2 warps over N (64 cols each)
    const int m0 = blockIdx.y * BM;
    const int n0 = blockIdx.x * BN;

    const int nkc = (g_kmax + 31) >> 5;  // dynamic k-chunk count (uniform)

    const float* Arow = g_feats + (size_t)m0 * KPAD;
    const float* Brow = g_Wt + (size_t)n0 * KPAD;

    const int ldr = tid >> 3;            // row (+32 per q)
    const int ldj = tid & 7;             // float4 column 0..7

    float acc[2][8][4];
#pragma unroll
    for (int i = 0; i < 2; i++)
#pragma unroll
        for (int j = 0; j < 8; j++)
#pragma unroll
            for (int v = 0; v < 4; v++) acc[i][j][v] = 0.f;

    auto issue_loads = [&](int buf, int kc) {
        const int kbase = kc * BK;
#pragma unroll
        for (int q = 0; q < 4; q++) {
            const int row = ldr + q * 32;
            const int so = swz(row, ldj * 4);
            cp_async16(&sA[buf][so], Arow + (size_t)row * KPAD + kbase + ldj * 4);
            cp_async16(&sB[buf][so], Brow + (size_t)row * KPAD + kbase + ldj * 4);
        }
        asm volatile("cp.async.commit_group;");
    };

    // ---- ldmatrix per-lane address precompute ----
    uint32_t sAu, sBu;
    asm("{ .reg .u64 t; cvta.to.shared.u64 t, %1; cvt.u32.u64 %0, t; }" : "=r"(sAu) : "l"((void*)sA));
    asm("{ .reg .u64 t; cvta.to.shared.u64 t, %1; cvt.u32.u64 %0, t; }" : "=r"(sBu) : "l"((void*)sB));

    const int xb = (lane & 7) << 2;
    const int rowA = warp_m * 32 + (lane & 15);
    const int aChunk = (lane >> 4) << 2;
    const uint32_t aBase = sAu + (uint32_t)rowA * 128;
    const int rowBoff = ((lane >> 4) << 3) + (lane & 7);
    const int bChunk = ((lane >> 3) & 1) << 2;
    uint32_t bBase[4];
#pragma unroll
    for (int jp = 0; jp < 4; jp++)
        bBase[jp] = sBu + (uint32_t)(warp_n * 64 + jp * 16 + rowBoff) * 128;

    issue_loads(0, 0);

    for (int kc = 0; kc < nkc; kc++) {
        const int buf = kc & 1;
        if (kc + 1 < nkc) {
            issue_loads(buf ^ 1, kc + 1);
            asm volatile("cp.async.wait_group 1;");
        } else {
            asm volatile("cp.async.wait_group 0;");
        }
        __syncthreads();

        const uint32_t bo = (uint32_t)buf * 16384u;
#pragma unroll
        for (int s = 0; s < 4; s++) {
            const uint32_t aOff = (uint32_t)(((s * 8 + aChunk) ^ xb) << 2);
            uint32_t a0[4], a1[4];
            ldsm4(a0[0], a0[1], a0[2], a0[3], aBase + bo + aOff);
            ldsm4(a1[0], a1[1], a1[2], a1[3], aBase + bo + aOff + 16 * 128);
            const uint32_t bOff = (uint32_t)(((s * 8 + bChunk) ^ xb) << 2);
#pragma unroll
            for (int jp = 0; jp < 4; jp++) {
                uint32_t b0, b1, b2, b3;
                ldsm4(b0, b1, b2, b3, bBase[jp] + bo + bOff);
                mma_tf32(acc[0][2 * jp],     a0, b0, b1);
                mma_tf32(acc[1][2 * jp],     a1, b0, b1);
                mma_tf32(acc[0][2 * jp + 1], a0, b2, b3);
                mma_tf32(acc[1][2 * jp + 1], a1, b2, b3);
            }
        }
        __syncthreads();
    }

    // epilogue
    const int lr = lane >> 2, lc = lane & 3;
#pragma unroll
    for (int i = 0; i < 2; i++) {
        const int row = m0 + warp_m * 32 + i * 16 + lr;
#pragma unroll
        for (int j = 0; j < 8; j++) {
            const int col = n0 + warp_n * 64 + j * 8 + lc * 2;
            const float2 bv = *reinterpret_cast<const float2*>(bias + col);
            float2 lo, hi;
            lo.x = acc[i][j][0] + bv.x;
            lo.y = acc[i][j][1] + bv.y;
            hi.x = acc[i][j][2] + bv.x;
            hi.y = acc[i][j][3] + bv.y;
            *reinterpret_cast<float2*>(out + (size_t)row * ND + col) = lo;
            *reinterpret_cast<float2*>(out + (size_t)(row + 8) * ND + col) = hi;
        }
    }
}

// ---------------- launch ----------------
extern "C" void kernel_launch(void* const* d_in, const int* in_sizes, int n_in,
                              void* d_out, int out_size) {
    (void)in_sizes; (void)n_in; (void)out_size;
    const float* img  = (const float*)d_in[0];
    const int*   seg  = (const int*)d_in[1];
    const float* Wsrc = (const float*)d_in[2];
    const float* bias = (const float*)d_in[3];
    float* out = (float*)d_out;

    hist_kernel<<<dim3(NCHUNK, NB), CPIX>>>(seg);
    scan_kernel<<<(NB * SSEG + 255) / 256, 256>>>();
    transpose_kernel<<<(ND * KPAD + 255) / 256, 256>>>(Wsrc);
    tail_zero_kernel<<<MTOT, 128>>>();
    scatter_kernel<<<dim3(NCHUNK, NB), CPIX>>>(img, seg);
    gemm_tf32_kernel<<<dim3(ND / BN, MTOT / BM), 256>>>(bias, out);
}

// round 5
// speedup vs baseline: 1.3585x; 1.1400x over previous
#include <cuda_runtime.h>
#include <cuda_fp16.h>
#include <cstdint>

// ---------------- problem constants ----------------
#define NB    64        // batch
#define SSEG  196       // segments
#define MP_   400       // max pixels per segment
#define ND    768       // embed dim
#define NCH   3         // channels
#define HW    50176     // 224*224
#define KPADH 1216      // K padded (halves), multiple of 64
#define KREAL 1200
#define MTOT  12544     // NB*SSEG
#define NCHUNK 98       // 50176/512
#define CPIX  512       // pixels per chunk

// GEMM tiling
#define BM 128
#define BN 128
#define BKH 64          // halves per k-chunk (=128 bytes per row)

// ---------------- scratch (device globals; no allocation) ----------------
__device__ __half g_feats[(size_t)MTOT * KPADH];  // ~30.5 MB, A matrix [M, KPADH]
__device__ __half g_Wt[(size_t)ND * KPADH];       // ~1.9 MB, B matrix [N, KPADH]
__device__ int    g_hist[NB * NCHUNK * SSEG];     // per-chunk histograms -> bases
__device__ int    g_cnt[MTOT];                    // per-(b,s) pixel count
__device__ int    g_kmax;                         // max over rows of 3*min(cnt,MP)

// ---------------- kernel 1: per-chunk segment histogram (+ reset g_kmax) ----------------
__global__ void hist_kernel(const int* __restrict__ seg) {
    __shared__ int h[SSEG];
    const int b = blockIdx.y, chunk = blockIdx.x;
    const int t = threadIdx.x;
    if (b == 0 && chunk == 0 && t == 0) g_kmax = 0;
    if (t < SSEG) h[t] = 0;
    __syncthreads();
    const int p = chunk * CPIX + t;
    const int s = seg[(size_t)b * HW + p];
    atomicAdd(&h[s], 1);
    __syncthreads();
    if (t < SSEG) g_hist[((size_t)b * NCHUNK + chunk) * SSEG + t] = h[t];
}

// ---------------- kernel 2: exclusive scan over chunks per (b,s); counts + kmax ----------------
__global__ void scan_kernel() {
    const int idx = blockIdx.x * blockDim.x + threadIdx.x;
    if (idx >= NB * SSEG) return;
    const int b = idx / SSEG, s = idx - b * SSEG;
    int run = 0;
    int* base = &g_hist[(size_t)b * NCHUNK * SSEG + s];
#pragma unroll 7
    for (int c = 0; c < NCHUNK; c++) {
        int* ptr = base + (size_t)c * SSEG;
        int v = *ptr;
        *ptr = run;
        run += v;
    }
    g_cnt[idx] = run;
    const int keff = (run < MP_ ? run : MP_) * 3;
    atomicMax(&g_kmax, keff);
}

// ---------------- kernel 3: W -> Wt [N][KPADH] (fp16), k = rank*3 + c permutation ----------------
__global__ void transpose_kernel(const float* __restrict__ Wsrc) {
    const int idx = blockIdx.x * blockDim.x + threadIdx.x;
    if (idx >= ND * KPADH) return;
    const int n = idx / KPADH, k = idx - n * KPADH;
    float v = 0.f;
    if (k < KREAL) {
        const int r = k / 3, c = k - 3 * r;           // k = r*3 + c
        v = Wsrc[(size_t)(c * MP_ + r) * ND + n];
    }
    g_Wt[(size_t)n * KPADH + k] = __float2half_rn(v);
}

// ---------------- kernel 4: zero only the unwritten tail of each feats row ----------------
__global__ void tail_zero_kernel() {
    const int row = blockIdx.x;
    int cnt = g_cnt[row];
    if (cnt > MP_) cnt = MP_;
    __half* dst = g_feats + (size_t)row * KPADH;
    int k0 = 3 * cnt;
    // scalar until 8-half (16B) aligned
    const int ka = (k0 + 7) & ~7;
    if (threadIdx.x < ka - k0) dst[k0 + threadIdx.x] = __ushort_as_half(0);
    uint4* v = reinterpret_cast<uint4*>(dst + ka);
    const int nv = (KPADH - ka) >> 3;
    const uint4 z = make_uint4(0u, 0u, 0u, 0u);
    for (int i = threadIdx.x; i < nv; i += blockDim.x) v[i] = z;
}

// ---------------- kernel 5: stable scatter of pixels into feats (fp16) ----------------
__global__ void scatter_kernel(const float* __restrict__ img, const int* __restrict__ seg) {
    __shared__ int wh[16][SSEG];     // per-warp histograms
    const int b = blockIdx.y, chunk = blockIdx.x;
    const int t = threadIdx.x;
    const int w = t >> 5, l = t & 31;
    for (int i = t; i < 16 * SSEG; i += CPIX) (&wh[0][0])[i] = 0;
    __syncthreads();

    const int p = chunk * CPIX + t;
    const int s = seg[(size_t)b * HW + p];

    // stable intra-warp rank (lane order == pixel order)
    const unsigned mask = __match_any_sync(0xffffffffu, s);
    const int lt = __popc(mask & ((1u << l) - 1u));
    const int leader = __ffs(mask) - 1;
    if (l == leader) atomicAdd(&wh[w][s], __popc(mask));
    __syncthreads();

    int pre = 0;
    for (int ww = 0; ww < w; ww++) pre += wh[ww][s];

    const int rank = g_hist[((size_t)b * NCHUNK + chunk) * SSEG + s] + pre + lt;
    if (rank < MP_) {
        __half* dst = g_feats + ((size_t)(b * SSEG + s)) * KPADH + rank * 3;
#pragma unroll
        for (int c = 0; c < NCH; c++) {
            const float v = img[((size_t)(b * NCH + c)) * HW + p];
            dst[c] = __float2half_rn(v);
        }
    }
}

// ---------------- kernel 6: fp16 mma.sync GEMM with ldmatrix feeds, dynamic K ----------------
// smem rows are 128B (64 halves); byte (r, 16B-granule g) stored at g ^ (r&7).
__device__ __forceinline__ void mma_fp16(float* d, const uint32_t* a, uint32_t b0, uint32_t b1) {
    asm volatile(
        "mma.sync.aligned.m16n8k16.row.col.f32.f16.f16.f32 "
        "{%0,%1,%2,%3}, {%4,%5,%6,%7}, {%8,%9}, {%0,%1,%2,%3};"
        : "+f"(d[0]), "+f"(d[1]), "+f"(d[2]), "+f"(d[3])
        : "r"(a[0]), "r"(a[1]), "r"(a[2]), "r"(a[3]), "r"(b0), "r"(b1));
}

__device__ __forceinline__ void ldsm4(uint32_t& r0, uint32_t& r1, uint32_t& r2, uint32_t& r3,
                                      uint32_t addr) {
    asm volatile("ldmatrix.sync.aligned.m8n8.x4.shared.b16 {%0,%1,%2,%3}, [%4];"
                 : "=r"(r0), "=r"(r1), "=r"(r2), "=r"(r3) : "r"(addr));
}

__device__ __forceinline__ void cp_async16s(uint32_t sa, const void* gptr) {
    asm volatile("cp.async.cg.shared.global [%0], [%1], 16;" :: "r"(sa), "l"(gptr));
}

// dynamic smem: [buf0: A 16KB | B 16KB][buf1: A 16KB | B 16KB] = 64KB
#define GEMM_SMEM 65536

__global__ void __launch_bounds__(256)
gemm_fp16_kernel(const float* __restrict__ bias, float* __restrict__ out) {
    extern __shared__ __align__(128) char smem[];
    uint32_t sbase;
    asm("{ .reg .u64 t; cvta.to.shared.u64 t, %1; cvt.u32.u64 %0, t; }" : "=r"(sbase) : "l"((void*)smem));

    const int tid = threadIdx.x;
    const int wid = tid >> 5, lane = tid & 31;
    const int warp_m = wid & 3;          // 4 warps over M (32 rows each)
    const int warp_n = wid >> 2;         // 2 warps over N (64 cols each)
    const int m0 = blockIdx.y * BM;
    const int n0 = blockIdx.x * BN;

    const int nkc = (g_kmax + BKH - 1) / BKH;   // dynamic k-chunk count (uniform)

    const __half* Arow = g_feats + (size_t)m0 * KPADH;
    const __half* Brow = g_Wt + (size_t)n0 * KPADH;

    // loader mapping: row = tid>>3 (+32 per q), 16B granule = tid&7
    const int ldr = tid >> 3;
    const int ldj = tid & 7;

    float acc[2][8][4];
#pragma unroll
    for (int i = 0; i < 2; i++)
#pragma unroll
        for (int j = 0; j < 8; j++)
#pragma unroll
            for (int v = 0; v < 4; v++) acc[i][j][v] = 0.f;

    auto issue_loads = [&](int buf, int kc) {
        const int kbase = kc * BKH;
        const uint32_t aDst = sbase + (uint32_t)buf * 32768u;
        const uint32_t bDst = aDst + 16384u;
#pragma unroll
        for (int q = 0; q < 4; q++) {
            const int row = ldr + q * 32;
            const uint32_t off = (uint32_t)row * 128u + (uint32_t)((ldj ^ (row & 7)) << 4);
            cp_async16s(aDst + off, Arow + (size_t)row * KPADH + kbase + ldj * 8);
            cp_async16s(bDst + off, Brow + (size_t)row * KPADH + kbase + ldj * 8);
        }
        asm volatile("cp.async.commit_group;");
    };

    // ---- ldmatrix per-lane invariants ----
    const int rowA = warp_m * 32 + (lane & 15);          // + 16 for second m-tile (same &7)
    const uint32_t aRowOff = (uint32_t)rowA * 128u;
    const int aXor = rowA & 7;
    const int aG = lane >> 4;                            // 0/1: k granule within k16
    int rowB[4], bXor[4];
    uint32_t bRowOff[4];
#pragma unroll
    for (int jp = 0; jp < 4; jp++) {
        rowB[jp] = warp_n * 64 + jp * 16 + ((lane >> 4) << 3) + (lane & 7);
        bRowOff[jp] = (uint32_t)rowB[jp] * 128u;
        bXor[jp] = rowB[jp] & 7;
    }
    const int bG = (lane >> 3) & 1;

    issue_loads(0, 0);

    for (int kc = 0; kc < nkc; kc++) {
        const int buf = kc & 1;
        if (kc + 1 < nkc) {
            issue_loads(buf ^ 1, kc + 1);
            asm volatile("cp.async.wait_group 1;");
        } else {
            asm volatile("cp.async.wait_group 0;");
        }
        __syncthreads();

        const uint32_t aBuf = sbase + (uint32_t)buf * 32768u;
        const uint32_t bBuf = aBuf + 16384u;
#pragma unroll
        for (int s = 0; s < 4; s++) {        // 4 k16-steps per 64-half chunk
            uint32_t a0[4], a1[4];
            const uint32_t aAddr = aBuf + aRowOff + (uint32_t)(((s * 2 + aG) ^ aXor) << 4);
            ldsm4(a0[0], a0[1], a0[2], a0[3], aAddr);
            ldsm4(a1[0], a1[1], a1[2], a1[3], aAddr + 16 * 128);
#pragma unroll
            for (int jp = 0; jp < 4; jp++) {
                uint32_t b0, b1, b2, b3;
                const uint32_t bAddr = bBuf + bRowOff[jp] + (uint32_t)(((s * 2 + bG) ^ bXor[jp]) << 4);
                ldsm4(b0, b1, b2, b3, bAddr);
                mma_fp16(acc[0][2 * jp],     a0, b0, b1);
                mma_fp16(acc[1][2 * jp],     a1, b0, b1);
                mma_fp16(acc[0][2 * jp + 1], a0, b2, b3);
                mma_fp16(acc[1][2 * jp + 1], a1, b2, b3);
            }
        }
        __syncthreads();
    }

    // epilogue: D(16x8) map: d0,d1 at (lane>>2, (lane&3)*2+{0,1}), d2,d3 at row+8
    const int lr = lane >> 2, lc = lane & 3;
#pragma unroll
    for (int i = 0; i < 2; i++) {
        const int row = m0 + warp_m * 32 + i * 16 + lr;
#pragma unroll
        for (int j = 0; j < 8; j++) {
            const int col = n0 + warp_n * 64 + j * 8 + lc * 2;
            const float2 bv = *reinterpret_cast<const float2*>(bias + col);
            float2 lo, hi;
            lo.x = acc[i][j][0] + bv.x;
            lo.y = acc[i][j][1] + bv.y;
            hi.x = acc[i][j][2] + bv.x;
            hi.y = acc[i][j][3] + bv.y;
            *reinterpret_cast<float2*>(out + (size_t)row * ND + col) = lo;
            *reinterpret_cast<float2*>(out + (size_t)(row + 8) * ND + col) = hi;
        }
    }
}

// ---------------- launch ----------------
extern "C" void kernel_launch(void* const* d_in, const int* in_sizes, int n_in,
                              void* d_out, int out_size) {
    (void)in_sizes; (void)n_in; (void)out_size;
    const float* img  = (const float*)d_in[0];
    const int*   seg  = (const int*)d_in[1];
    const float* Wsrc = (const float*)d_in[2];
    const float* bias = (const float*)d_in[3];
    float* out = (float*)d_out;

    cudaFuncSetAttribute(gemm_fp16_kernel, cudaFuncAttributeMaxDynamicSharedMemorySize, GEMM_SMEM);

    hist_kernel<<<dim3(NCHUNK, NB), CPIX>>>(seg);
    scan_kernel<<<(NB * SSEG + 255) / 256, 256>>>();
    transpose_kernel<<<(ND * KPADH + 255) / 256, 256>>>(Wsrc);
    tail_zero_kernel<<<MTOT, 64>>>();
    scatter_kernel<<<dim3(NCHUNK, NB), CPIX>>>(img, seg);
    gemm_fp16_kernel<<<dim3(ND / BN, MTOT / BM), 256, GEMM_SMEM>>>(bias, out);
}

// round 6
// speedup vs baseline: 1.6185x; 1.1914x over previous
#include <cuda_runtime.h>
#include <cuda_fp16.h>
#include <cstdint>

// ---------------- problem constants ----------------
#define NB    64        // batch
#define SSEG  196       // segments
#define MP_   400       // max pixels per segment
#define ND    768       // embed dim
#define NCH   3         // channels
#define HW    50176     // 224*224
#define KPADH 1216      // K padded (halves), multiple of 64
#define KREAL 1200
#define MTOT  12544     // NB*SSEG
#define NCHUNK 98       // 50176/512
#define CPIX  512       // pixels per chunk

// GEMM tiling
#define BM 128
#define BN 128
#define BKH 64          // halves per k-chunk (=128 bytes per row)

// ---------------- scratch (device globals; no allocation) ----------------
__device__ __half g_feats[(size_t)MTOT * KPADH];  // ~30.5 MB, A matrix [M, KPADH]
__device__ __half g_Wt[(size_t)ND * KPADH];       // ~1.9 MB, B matrix [N, KPADH]
__device__ int    g_hist[NB * NCHUNK * SSEG];     // per-chunk histograms -> bases
__device__ int    g_cnt[MTOT];                    // per-(b,s) pixel count
__device__ int    g_kmax;                         // max over rows of 3*min(cnt,MP)

// ---------------- kernel 1: per-chunk segment histogram (+ reset g_kmax) ----------------
__global__ void hist_kernel(const int* __restrict__ seg) {
    __shared__ int h[SSEG];
    const int b = blockIdx.y, chunk = blockIdx.x;
    const int t = threadIdx.x;
    if (b == 0 && chunk == 0 && t == 0) g_kmax = 0;
    if (t < SSEG) h[t] = 0;
    __syncthreads();
    const int p = chunk * CPIX + t;
    const int s = seg[(size_t)b * HW + p];
    atomicAdd(&h[s], 1);
    __syncthreads();
    if (t < SSEG) g_hist[((size_t)b * NCHUNK + chunk) * SSEG + t] = h[t];
}

// ---------------- kernel 2: exclusive scan over chunks per (b,s); counts + kmax ----------------
__global__ void scan_kernel() {
    const int idx = blockIdx.x * blockDim.x + threadIdx.x;
    if (idx >= NB * SSEG) return;
    const int b = idx / SSEG, s = idx - b * SSEG;
    int run = 0;
    int* base = &g_hist[(size_t)b * NCHUNK * SSEG + s];
#pragma unroll 7
    for (int c = 0; c < NCHUNK; c++) {
        int* ptr = base + (size_t)c * SSEG;
        int v = *ptr;
        *ptr = run;
        run += v;
    }
    g_cnt[idx] = run;
    const int keff = (run < MP_ ? run : MP_) * 3;
    atomicMax(&g_kmax, keff);
}

// ---------------- kernel 3: W -> Wt [N][KPADH] (fp16), k = rank*3 + c, smem tiled ----------------
__global__ void transpose_kernel(const float* __restrict__ Wsrc) {
    __shared__ float tile[32][33];
    const int k0 = blockIdx.x * 32;      // K tile (0..KPADH)
    const int n0 = blockIdx.y * 32;      // N tile
    const int tx = threadIdx.x, ty = threadIdx.y;   // 32 x 8
#pragma unroll
    for (int q = 0; q < 4; q++) {
        const int kk = k0 + ty + q * 8;
        float v = 0.f;
        if (kk < KREAL) {
            const int r = kk / 3, c = kk - 3 * r;   // kk = r*3 + c
            v = Wsrc[(size_t)(c * MP_ + r) * ND + n0 + tx];
        }
        tile[ty + q * 8][tx] = v;
    }
    __syncthreads();
#pragma unroll
    for (int q = 0; q < 4; q++) {
        const int n = n0 + ty + q * 8;
        g_Wt[(size_t)n * KPADH + k0 + tx] = __float2half_rn(tile[tx][ty + q * 8]);
    }
}

// ---------------- kernel 4: stable scatter of pixels into feats (fp16, 2-store) ----------------
__global__ void scatter_kernel(const float* __restrict__ img, const int* __restrict__ seg) {
    __shared__ int wh[16][SSEG];     // per-warp histograms
    const int b = blockIdx.y, chunk = blockIdx.x;
    const int t = threadIdx.x;
    const int w = t >> 5, l = t & 31;
    for (int i = t; i < 16 * SSEG; i += CPIX) (&wh[0][0])[i] = 0;
    __syncthreads();

    const int p = chunk * CPIX + t;
    const int s = seg[(size_t)b * HW + p];

    // stable intra-warp rank (lane order == pixel order)
    const unsigned mask = __match_any_sync(0xffffffffu, s);
    const int lt = __popc(mask & ((1u << l) - 1u));
    const int leader = __ffs(mask) - 1;
    if (l == leader) atomicAdd(&wh[w][s], __popc(mask));
    __syncthreads();

    int pre = 0;
    for (int ww = 0; ww < w; ww++) pre += wh[ww][s];

    const int rank = g_hist[((size_t)b * NCHUNK + chunk) * SSEG + s] + pre + lt;
    if (rank < MP_) {
        const __half h0 = __float2half_rn(img[((size_t)(b * NCH + 0)) * HW + p]);
        const __half h1 = __float2half_rn(img[((size_t)(b * NCH + 1)) * HW + p]);
        const __half h2 = __float2half_rn(img[((size_t)(b * NCH + 2)) * HW + p]);
        __half* dst = g_feats + ((size_t)(b * SSEG + s)) * KPADH + rank * 3;
        if (rank & 1) {
            dst[0] = h0;
            *reinterpret_cast<__half2*>(dst + 1) = __halves2half2(h1, h2);
        } else {
            *reinterpret_cast<__half2*>(dst) = __halves2half2(h0, h1);
            dst[2] = h2;
        }
    }
}

// ---------------- kernel 5: fp16 mma.sync GEMM, ldmatrix feeds, dynamic K, zero-fill A ----------------
__device__ __forceinline__ void mma_fp16(float* d, const uint32_t* a, uint32_t b0, uint32_t b1) {
    asm volatile(
        "mma.sync.aligned.m16n8k16.row.col.f32.f16.f16.f32 "
        "{%0,%1,%2,%3}, {%4,%5,%6,%7}, {%8,%9}, {%0,%1,%2,%3};"
        : "+f"(d[0]), "+f"(d[1]), "+f"(d[2]), "+f"(d[3])
        : "r"(a[0]), "r"(a[1]), "r"(a[2]), "r"(a[3]), "r"(b0), "r"(b1));
}

__device__ __forceinline__ void ldsm4(uint32_t& r0, uint32_t& r1, uint32_t& r2, uint32_t& r3,
                                      uint32_t addr) {
    asm volatile("ldmatrix.sync.aligned.m8n8.x4.shared.b16 {%0,%1,%2,%3}, [%4];"
                 : "=r"(r0), "=r"(r1), "=r"(r2), "=r"(r3) : "r"(addr));
}

__device__ __forceinline__ void cp_async16(uint32_t sa, const void* gptr) {
    asm volatile("cp.async.cg.shared.global [%0], [%1], 16;" :: "r"(sa), "l"(gptr));
}
__device__ __forceinline__ void cp_async16z(uint32_t sa, const void* gptr, int src_bytes) {
    asm volatile("cp.async.cg.shared.global [%0], [%1], 16, %2;" :: "r"(sa), "l"(gptr), "r"(src_bytes));
}

// dynamic smem: [buf0: A 16KB | B 16KB][buf1: A 16KB | B 16KB] = 64KB
#define GEMM_SMEM 65536

__global__ void __launch_bounds__(256)
gemm_fp16_kernel(const float* __restrict__ bias, float* __restrict__ out) {
    extern __shared__ __align__(128) char smem[];
    uint32_t sbase;
    asm("{ .reg .u64 t; cvta.to.shared.u64 t, %1; cvt.u32.u64 %0, t; }" : "=r"(sbase) : "l"((void*)smem));

    const int tid = threadIdx.x;
    const int wid = tid >> 5, lane = tid & 31;
    const int warp_m = wid & 3;          // 4 warps over M (32 rows each)
    const int warp_n = wid >> 2;         // 2 warps over N (64 cols each)
    const int m0 = blockIdx.y * BM;
    const int n0 = blockIdx.x * BN;

    const int nkc = (g_kmax + BKH - 1) / BKH;   // dynamic k-chunk count (uniform)

    const __half* Arow = g_feats + (size_t)m0 * KPADH;
    const __half* Brow = g_Wt + (size_t)n0 * KPADH;

    // loader mapping: row = tid>>3 (+32 per q), 16B granule = tid&7
    const int ldr = tid >> 3;
    const int ldj = tid & 7;

    // per-loader-row valid byte counts (A zero-fill)
    int avb[4];
#pragma unroll
    for (int q = 0; q < 4; q++) {
        int c = g_cnt[m0 + ldr + q * 32];
        if (c > MP_) c = MP_;
        avb[q] = 6 * c - ldj * 16;       // bytes valid at granule ldj, before k-chunk offset
    }

    float acc[2][8][4];
#pragma unroll
    for (int i = 0; i < 2; i++)
#pragma unroll
        for (int j = 0; j < 8; j++)
#pragma unroll
            for (int v = 0; v < 4; v++) acc[i][j][v] = 0.f;

    auto issue_loads = [&](int buf, int kc) {
        const int kbase = kc * BKH;
        const int kbyte = kc * 128;
        const uint32_t aDst = sbase + (uint32_t)buf * 32768u;
        const uint32_t bDst = aDst + 16384u;
#pragma unroll
        for (int q = 0; q < 4; q++) {
            const int row = ldr + q * 32;
            const uint32_t off = (uint32_t)row * 128u + (uint32_t)((ldj ^ (row & 7)) << 4);
            int av = avb[q] - kbyte;
            av = av < 0 ? 0 : (av > 16 ? 16 : av);
            cp_async16z(aDst + off, Arow + (size_t)row * KPADH + kbase + ldj * 8, av);
            cp_async16(bDst + off, Brow + (size_t)row * KPADH + kbase + ldj * 8);
        }
        asm volatile("cp.async.commit_group;");
    };

    // ---- ldmatrix per-lane invariants ----
    const int rowA = warp_m * 32 + (lane & 15);
    const uint32_t aRowOff = (uint32_t)rowA * 128u;
    const int aXor = rowA & 7;
    const int aG = lane >> 4;
    int bXor[4];
    uint32_t bRowOff[4];
#pragma unroll
    for (int jp = 0; jp < 4; jp++) {
        const int rowB = warp_n * 64 + jp * 16 + ((lane >> 4) << 3) + (lane & 7);
        bRowOff[jp] = (uint32_t)rowB * 128u;
        bXor[jp] = rowB & 7;
    }
    const int bG = (lane >> 3) & 1;

    issue_loads(0, 0);

    for (int kc = 0; kc < nkc; kc++) {
        const int buf = kc & 1;
        if (kc + 1 < nkc) {
            issue_loads(buf ^ 1, kc + 1);
            asm volatile("cp.async.wait_group 1;");
        } else {
            asm volatile("cp.async.wait_group 0;");
        }
        __syncthreads();

        const uint32_t aBuf = sbase + (uint32_t)buf * 32768u;
        const uint32_t bBuf = aBuf + 16384u;
#pragma unroll
        for (int s = 0; s < 4; s++) {        // 4 k16-steps per 64-half chunk
            uint32_t a0[4], a1[4];
            const uint32_t aAddr = aBuf + aRowOff + (uint32_t)(((s * 2 + aG) ^ aXor) << 4);
            ldsm4(a0[0], a0[1], a0[2], a0[3], aAddr);
            ldsm4(a1[0], a1[1], a1[2], a1[3], aAddr + 16 * 128);
#pragma unroll
            for (int jp = 0; jp < 4; jp++) {
                uint32_t b0, b1, b2, b3;
                const uint32_t bAddr = bBuf + bRowOff[jp] + (uint32_t)(((s * 2 + bG) ^ bXor[jp]) << 4);
                ldsm4(b0, b1, b2, b3, bAddr);
                mma_fp16(acc[0][2 * jp],     a0, b0, b1);
                mma_fp16(acc[1][2 * jp],     a1, b0, b1);
                mma_fp16(acc[0][2 * jp + 1], a0, b2, b3);
                mma_fp16(acc[1][2 * jp + 1], a1, b2, b3);
            }
        }
        __syncthreads();
    }

    // epilogue
    const int lr = lane >> 2, lc = lane & 3;
#pragma unroll
    for (int i = 0; i < 2; i++) {
        const int row = m0 + warp_m * 32 + i * 16 + lr;
#pragma unroll
        for (int j = 0; j < 8; j++) {
            const int col = n0 + warp_n * 64 + j * 8 + lc * 2;
            const float2 bv = *reinterpret_cast<const float2*>(bias + col);
            float2 lo, hi;
            lo.x = acc[i][j][0] + bv.x;
            lo.y = acc[i][j][1] + bv.y;
            hi.x = acc[i][j][2] + bv.x;
            hi.y = acc[i][j][3] + bv.y;
            *reinterpret_cast<float2*>(out + (size_t)row * ND + col) = lo;
            *reinterpret_cast<float2*>(out + (size_t)(row + 8) * ND + col) = hi;
        }
    }
}

// ---------------- launch ----------------
extern "C" void kernel_launch(void* const* d_in, const int* in_sizes, int n_in,
                              void* d_out, int out_size) {
    (void)in_sizes; (void)n_in; (void)out_size;
    const float* img  = (const float*)d_in[0];
    const int*   seg  = (const int*)d_in[1];
    const float* Wsrc = (const float*)d_in[2];
    const float* bias = (const float*)d_in[3];
    float* out = (float*)d_out;

    cudaFuncSetAttribute(gemm_fp16_kernel, cudaFuncAttributeMaxDynamicSharedMemorySize, GEMM_SMEM);

    hist_kernel<<<dim3(NCHUNK, NB), CPIX>>>(seg);
    scan_kernel<<<(NB * SSEG + 255) / 256, 256>>>();
    transpose_kernel<<<dim3(KPADH / 32, ND / 32), dim3(32, 8)>>>(Wsrc);
    scatter_kernel<<<dim3(NCHUNK, NB), CPIX>>>(img, seg);
    gemm_fp16_kernel<<<dim3(ND / BN, MTOT / BM), 256, GEMM_SMEM>>>(bias, out);
}

// round 7
// speedup vs baseline: 1.6604x; 1.0259x over previous
#include <cuda_runtime.h>
#include <cuda_fp16.h>
#include <cstdint>

// ---------------- problem constants ----------------
#define NB    64        // batch
#define SSEG  196       // segments
#define MP_   400       // max pixels per segment
#define ND    768       // embed dim
#define NCH   3         // channels
#define HW    50176     // 224*224
#define KPADH 1216      // K padded (halves), multiple of 64
#define KREAL 1200
#define MTOT  12544     // NB*SSEG
#define NCHUNK 98       // 50176/512
#define CPIX  512       // pixels per chunk

// GEMM tiling
#define BM 128
#define BN 128
#define BKH 64          // halves per k-chunk (=128 bytes per row)

// ---------------- scratch (device globals; no allocation) ----------------
__device__ __half g_feats[(size_t)MTOT * KPADH];  // ~30.5 MB, A matrix [M, KPADH]
__device__ __half g_Wt[(size_t)ND * KPADH];       // ~1.9 MB, B matrix [N, KPADH]
__device__ int    g_hist[NB * NCHUNK * SSEG];     // per-chunk histograms -> bases
__device__ int    g_cnt[MTOT];                    // per-(b,s) pixel count
__device__ int    g_bins[402];                    // counting-sort bins (key = 400 - min(cnt,400))
__device__ int    g_perm[MTOT];                   // row permutation, sorted by cnt desc

// ---------------- kernel 1: per-chunk segment histogram ----------------
__global__ void hist_kernel(const int* __restrict__ seg) {
    __shared__ int h[SSEG];
    const int b = blockIdx.y, chunk = blockIdx.x;
    const int t = threadIdx.x;
    if (t < SSEG) h[t] = 0;
    __syncthreads();
    const int p = chunk * CPIX + t;
    const int s = seg[(size_t)b * HW + p];
    atomicAdd(&h[s], 1);
    __syncthreads();
    if (t < SSEG) g_hist[((size_t)b * NCHUNK + chunk) * SSEG + t] = h[t];
}

// ---------------- kernel 2: exclusive scan over chunks per (b,s); counts; reset bins ----------------
__global__ void scan_kernel() {
    const int idx = blockIdx.x * blockDim.x + threadIdx.x;
    if (idx < 402) g_bins[idx] = 0;
    if (idx >= NB * SSEG) return;
    const int b = idx / SSEG, s = idx - b * SSEG;
    int run = 0;
    int* base = &g_hist[(size_t)b * NCHUNK * SSEG + s];
#pragma unroll 7
    for (int c = 0; c < NCHUNK; c++) {
        int* ptr = base + (size_t)c * SSEG;
        int v = *ptr;
        *ptr = run;
        run += v;
    }
    g_cnt[idx] = run;
}

// ---------------- sort kernels: counting sort of rows by cnt (descending) ----------------
__global__ void sort_hist_kernel() {
    const int idx = blockIdx.x * blockDim.x + threadIdx.x;
    if (idx >= MTOT) return;
    int c = g_cnt[idx];
    if (c > MP_) c = MP_;
    atomicAdd(&g_bins[MP_ - c], 1);
}

__global__ void sort_scan_kernel() {     // 1 block, 512 threads
    __shared__ int sm[512];
    const int t = threadIdx.x;
    const int orig = (t < 402) ? g_bins[t] : 0;
    sm[t] = orig;
    __syncthreads();
    for (int off = 1; off < 512; off <<= 1) {
        int v = (t >= off) ? sm[t - off] : 0;
        __syncthreads();
        sm[t] += v;
        __syncthreads();
    }
    if (t < 402) g_bins[t] = sm[t] - orig;   // exclusive
}

__global__ void sort_place_kernel() {
    const int idx = blockIdx.x * blockDim.x + threadIdx.x;
    if (idx >= MTOT) return;
    int c = g_cnt[idx];
    if (c > MP_) c = MP_;
    const int pos = atomicAdd(&g_bins[MP_ - c], 1);
    g_perm[pos] = idx;
}

// ---------------- kernel 3: W -> Wt [N][KPADH] (fp16), k = rank*3 + c, smem tiled ----------------
__global__ void transpose_kernel(const float* __restrict__ Wsrc) {
    __shared__ float tile[32][33];
    const int k0 = blockIdx.x * 32;      // K tile (0..KPADH)
    const int n0 = blockIdx.y * 32;      // N tile
    const int tx = threadIdx.x, ty = threadIdx.y;   // 32 x 8
#pragma unroll
    for (int q = 0; q < 4; q++) {
        const int kk = k0 + ty + q * 8;
        float v = 0.f;
        if (kk < KREAL) {
            const int r = kk / 3, c = kk - 3 * r;   // kk = r*3 + c
            v = Wsrc[(size_t)(c * MP_ + r) * ND + n0 + tx];
        }
        tile[ty + q * 8][tx] = v;
    }
    __syncthreads();
#pragma unroll
    for (int q = 0; q < 4; q++) {
        const int n = n0 + ty + q * 8;
        g_Wt[(size_t)n * KPADH + k0 + tx] = __float2half_rn(tile[tx][ty + q * 8]);
    }
}

// ---------------- kernel 4: stable scatter of pixels into feats (fp16, 2-store) ----------------
__global__ void scatter_kernel(const float* __restrict__ img, const int* __restrict__ seg) {
    __shared__ int wh[16][SSEG];     // per-warp histograms
    const int b = blockIdx.y, chunk = blockIdx.x;
    const int t = threadIdx.x;
    const int w = t >> 5, l = t & 31;
    for (int i = t; i < 16 * SSEG; i += CPIX) (&wh[0][0])[i] = 0;
    __syncthreads();

    const int p = chunk * CPIX + t;
    const int s = seg[(size_t)b * HW + p];

    // stable intra-warp rank (lane order == pixel order)
    const unsigned mask = __match_any_sync(0xffffffffu, s);
    const int lt = __popc(mask & ((1u << l) - 1u));
    const int leader = __ffs(mask) - 1;
    if (l == leader) atomicAdd(&wh[w][s], __popc(mask));
    __syncthreads();

    // fully unrolled predicated prefix over warps (independent LDS, one latency)
    int pre = 0;
#pragma unroll
    for (int ww = 0; ww < 15; ww++) {
        const int v = wh[ww][s];
        pre += (ww < w) ? v : 0;
    }

    const int rank = g_hist[((size_t)b * NCHUNK + chunk) * SSEG + s] + pre + lt;
    if (rank < MP_) {
        const __half h0 = __float2half_rn(img[((size_t)(b * NCH + 0)) * HW + p]);
        const __half h1 = __float2half_rn(img[((size_t)(b * NCH + 1)) * HW + p]);
        const __half h2 = __float2half_rn(img[((size_t)(b * NCH + 2)) * HW + p]);
        __half* dst = g_feats + ((size_t)(b * SSEG + s)) * KPADH + rank * 3;
        if (rank & 1) {
            dst[0] = h0;
            *reinterpret_cast<__half2*>(dst + 1) = __halves2half2(h1, h2);
        } else {
            *reinterpret_cast<__half2*>(dst) = __halves2half2(h0, h1);
            dst[2] = h2;
        }
    }
}

// ---------------- kernel 5: fp16 mma.sync GEMM, perm rows, per-tile dynamic K ----------------
__device__ __forceinline__ void mma_fp16(float* d, const uint32_t* a, uint32_t b0, uint32_t b1) {
    asm volatile(
        "mma.sync.aligned.m16n8k16.row.col.f32.f16.f16.f32 "
        "{%0,%1,%2,%3}, {%4,%5,%6,%7}, {%8,%9}, {%0,%1,%2,%3};"
        : "+f"(d[0]), "+f"(d[1]), "+f"(d[2]), "+f"(d[3])
        : "r"(a[0]), "r"(a[1]), "r"(a[2]), "r"(a[3]), "r"(b0), "r"(b1));
}

__device__ __forceinline__ void ldsm4(uint32_t& r0, uint32_t& r1, uint32_t& r2, uint32_t& r3,
                                      uint32_t addr) {
    asm volatile("ldmatrix.sync.aligned.m8n8.x4.shared.b16 {%0,%1,%2,%3}, [%4];"
                 : "=r"(r0), "=r"(r1), "=r"(r2), "=r"(r3) : "r"(addr));
}

__device__ __forceinline__ void cp_async16(uint32_t sa, const void* gptr) {
    asm volatile("cp.async.cg.shared.global [%0], [%1], 16;" :: "r"(sa), "l"(gptr));
}
__device__ __forceinline__ void cp_async16z(uint32_t sa, const void* gptr, int src_bytes) {
    asm volatile("cp.async.cg.shared.global [%0], [%1], 16, %2;" :: "r"(sa), "l"(gptr), "r"(src_bytes));
}

// dynamic smem: [buf0: A 16KB | B 16KB][buf1: A 16KB | B 16KB] = 64KB
#define GEMM_SMEM 65536

__global__ void __launch_bounds__(256)
gemm_fp16_kernel(const float* __restrict__ bias, float* __restrict__ out) {
    extern __shared__ __align__(128) char smem[];
    uint32_t sbase;
    asm("{ .reg .u64 t; cvta.to.shared.u64 t, %1; cvt.u32.u64 %0, t; }" : "=r"(sbase) : "l"((void*)smem));

    __shared__ int s_km;

    const int tid = threadIdx.x;
    const int wid = tid >> 5, lane = tid & 31;
    const int warp_m = wid & 3;          // 4 warps over M (32 rows each)
    const int warp_n = wid >> 2;         // 2 warps over N (64 cols each)
    const int m0 = blockIdx.y * BM;
    const int n0 = blockIdx.x * BN;

    if (tid == 0) s_km = BKH;            // at least one chunk

    const __half* Brow = g_Wt + (size_t)n0 * KPADH;

    // loader mapping: row = tid>>3 (+32 per q), 16B granule = tid&7
    const int ldr = tid >> 3;
    const int ldj = tid & 7;

    // permuted row pointers + valid byte counts for A loader
    const __half* aptr[4];
    int avb[4];
#pragma unroll
    for (int q = 0; q < 4; q++) {
        const int pr = g_perm[m0 + ldr + q * 32];
        aptr[q] = g_feats + (size_t)pr * KPADH;
        int c = g_cnt[pr];
        if (c > MP_) c = MP_;
        avb[q] = 6 * c - ldj * 16;       // bytes valid at granule ldj, before k-chunk offset
    }
    // per-tile kmax over the 128 permuted rows
    if (tid < BM) {
        int c = g_cnt[g_perm[m0 + tid]];
        if (c > MP_) c = MP_;
        atomicMax(&s_km, 3 * c);
    }

    float acc[2][8][4];
#pragma unroll
    for (int i = 0; i < 2; i++)
#pragma unroll
        for (int j = 0; j < 8; j++)
#pragma unroll
            for (int v = 0; v < 4; v++) acc[i][j][v] = 0.f;

    auto issue_loads = [&](int buf, int kc) {
        const int kbase = kc * BKH;
        const int kbyte = kc * 128;
        const uint32_t aDst = sbase + (uint32_t)buf * 32768u;
        const uint32_t bDst = aDst + 16384u;
#pragma unroll
        for (int q = 0; q < 4; q++) {
            const int row = ldr + q * 32;
            const uint32_t off = (uint32_t)row * 128u + (uint32_t)((ldj ^ (row & 7)) << 4);
            int av = avb[q] - kbyte;
            av = av < 0 ? 0 : (av > 16 ? 16 : av);
            cp_async16z(aDst + off, aptr[q] + kbase + ldj * 8, av);
            cp_async16(bDst + off, Brow + (size_t)row * KPADH + kbase + ldj * 8);
        }
        asm volatile("cp.async.commit_group;");
    };

    issue_loads(0, 0);
    __syncthreads();                      // publish s_km
    const int nkc = (s_km + BKH - 1) / BKH;

    // ---- ldmatrix per-lane invariants ----
    const int rowA = warp_m * 32 + (lane & 15);
    const uint32_t aRowOff = (uint32_t)rowA * 128u;
    const int aXor = rowA & 7;
    const int aG = lane >> 4;
    int bXor[4];
    uint32_t bRowOff[4];
#pragma unroll
    for (int jp = 0; jp < 4; jp++) {
        const int rowB = warp_n * 64 + jp * 16 + ((lane >> 4) << 3) + (lane & 7);
        bRowOff[jp] = (uint32_t)rowB * 128u;
        bXor[jp] = rowB & 7;
    }
    const int bG = (lane >> 3) & 1;

    for (int kc = 0; kc < nkc; kc++) {
        const int buf = kc & 1;
        if (kc + 1 < nkc) {
            issue_loads(buf ^ 1, kc + 1);
            asm volatile("cp.async.wait_group 1;");
        } else {
            asm volatile("cp.async.wait_group 0;");
        }
        __syncthreads();

        const uint32_t aBuf = sbase + (uint32_t)buf * 32768u;
        const uint32_t bBuf = aBuf + 16384u;
#pragma unroll
        for (int s = 0; s < 4; s++) {        // 4 k16-steps per 64-half chunk
            uint32_t a0[4], a1[4];
            const uint32_t aAddr = aBuf + aRowOff + (uint32_t)(((s * 2 + aG) ^ aXor) << 4);
            ldsm4(a0[0], a0[1], a0[2], a0[3], aAddr);
            ldsm4(a1[0], a1[1], a1[2], a1[3], aAddr + 16 * 128);
#pragma unroll
            for (int jp = 0; jp < 4; jp++) {
                uint32_t b0, b1, b2, b3;
                const uint32_t bAddr = bBuf + bRowOff[jp] + (uint32_t)(((s * 2 + bG) ^ bXor[jp]) << 4);
                ldsm4(b0, b1, b2, b3, bAddr);
                mma_fp16(acc[0][2 * jp],     a0, b0, b1);
                mma_fp16(acc[1][2 * jp],     a1, b0, b1);
                mma_fp16(acc[0][2 * jp + 1], a0, b2, b3);
                mma_fp16(acc[1][2 * jp + 1], a1, b2, b3);
            }
        }
        __syncthreads();
    }

    // epilogue: rows go back to their original positions via perm
    const int lr = lane >> 2, lc = lane & 3;
#pragma unroll
    for (int i = 0; i < 2; i++) {
        const int rowLo = g_perm[m0 + warp_m * 32 + i * 16 + lr];
        const int rowHi = g_perm[m0 + warp_m * 32 + i * 16 + lr + 8];
#pragma unroll
        for (int j = 0; j < 8; j++) {
            const int col = n0 + warp_n * 64 + j * 8 + lc * 2;
            const float2 bv = *reinterpret_cast<const float2*>(bias + col);
            float2 lo, hi;
            lo.x = acc[i][j][0] + bv.x;
            lo.y = acc[i][j][1] + bv.y;
            hi.x = acc[i][j][2] + bv.x;
            hi.y = acc[i][j][3] + bv.y;
            *reinterpret_cast<float2*>(out + (size_t)rowLo * ND + col) = lo;
            *reinterpret_cast<float2*>(out + (size_t)rowHi * ND + col) = hi;
        }
    }
}

// ---------------- launch ----------------
extern "C" void kernel_launch(void* const* d_in, const int* in_sizes, int n_in,
                              void* d_out, int out_size) {
    (void)in_sizes; (void)n_in; (void)out_size;
    const float* img  = (const float*)d_in[0];
    const int*   seg  = (const int*)d_in[1];
    const float* Wsrc = (const float*)d_in[2];
    const float* bias = (const float*)d_in[3];
    float* out = (float*)d_out;

    cudaFuncSetAttribute(gemm_fp16_kernel, cudaFuncAttributeMaxDynamicSharedMemorySize, GEMM_SMEM);

    hist_kernel<<<dim3(NCHUNK, NB), CPIX>>>(seg);
    scan_kernel<<<(NB * SSEG + 255) / 256, 256>>>();
    sort_hist_kernel<<<(MTOT + 255) / 256, 256>>>();
    sort_scan_kernel<<<1, 512>>>();
    sort_place_kernel<<<(MTOT + 255) / 256, 256>>>();
    transpose_kernel<<<dim3(KPADH / 32, ND / 32), dim3(32, 8)>>>(Wsrc);
    scatter_kernel<<<dim3(NCHUNK, NB), CPIX>>>(img, seg);
    gemm_fp16_kernel<<<dim3(ND / BN, MTOT / BM), 256, GEMM_SMEM>>>(bias, out);
}